// round 4
// baseline (speedup 1.0000x reference)
#include <cuda_runtime.h>
#include <cuda_bf16.h>
#include <cstdint>

// ---------------------------------------------------------------------------
// out[n] = (segment_sum(pred_prob[src], dst)[n] - 1)^2 * special_cost[n]
// N = 1,000,000 nodes, E = 16,000,000 edges.
// init out to -1, RED-scatter pred_prob[src[e]] into out[dst[e]],
// epilogue out[n] = out[n]^2 * special_cost[n].
// Bottleneck model (calibrated R2): scatter is L1tex-wavefront bound,
// ~2.3 cyc/edge/SM for (random gather + random RED).
// ---------------------------------------------------------------------------

__device__ __forceinline__ void red_add_f32(float* ptr, float val) {
    asm volatile("red.global.relaxed.gpu.add.f32 [%0], %1;"
                 :: "l"(ptr), "f"(val) : "memory");
}

__global__ __launch_bounds__(512) void init_kernel(float* __restrict__ out, int n4) {
    int i = blockIdx.x * blockDim.x + threadIdx.x;
    if (i < n4) {
        reinterpret_cast<float4*>(out)[i] =
            make_float4(-1.0f, -1.0f, -1.0f, -1.0f);
    }
}

__global__ __launch_bounds__(512) void scatter_kernel(
        const float* __restrict__ pred_prob,
        const int*   __restrict__ src,
        const int*   __restrict__ dst,
        float*       __restrict__ out,
        int num_edges) {
    // 8 edges per thread: 2x int4 per index stream (coalesced 16B), then
    // 8 random gathers + 8 random REDs. Front-batch the loads for MLP.
    int i = blockIdx.x * blockDim.x + threadIdx.x;
    int base = i * 8;
    if (base + 7 < num_edges) {
        const int4* s4p = reinterpret_cast<const int4*>(src + base);
        const int4* d4p = reinterpret_cast<const int4*>(dst + base);
        int4 sa = s4p[0];
        int4 sb = s4p[1];
        int4 da = d4p[0];
        int4 db = d4p[1];
        float m0 = __ldg(pred_prob + sa.x);
        float m1 = __ldg(pred_prob + sa.y);
        float m2 = __ldg(pred_prob + sa.z);
        float m3 = __ldg(pred_prob + sa.w);
        float m4 = __ldg(pred_prob + sb.x);
        float m5 = __ldg(pred_prob + sb.y);
        float m6 = __ldg(pred_prob + sb.z);
        float m7 = __ldg(pred_prob + sb.w);
        red_add_f32(out + da.x, m0);
        red_add_f32(out + da.y, m1);
        red_add_f32(out + da.z, m2);
        red_add_f32(out + da.w, m3);
        red_add_f32(out + db.x, m4);
        red_add_f32(out + db.y, m5);
        red_add_f32(out + db.z, m6);
        red_add_f32(out + db.w, m7);
    } else {
        for (int e = base; e < num_edges; ++e) {
            red_add_f32(out + dst[e], __ldg(pred_prob + src[e]));
        }
    }
}

__global__ __launch_bounds__(512) void apply_kernel(
        float* __restrict__ out,
        const float* __restrict__ special_cost,
        int n4) {
    int i = blockIdx.x * blockDim.x + threadIdx.x;
    if (i < n4) {
        float4 h = reinterpret_cast<const float4*>(out)[i];
        float4 c = reinterpret_cast<const float4*>(special_cost)[i];
        h.x = h.x * h.x * c.x;
        h.y = h.y * h.y * c.y;
        h.z = h.z * h.z * c.z;
        h.w = h.w * h.w * c.w;
        reinterpret_cast<float4*>(out)[i] = h;
    }
}

extern "C" void kernel_launch(void* const* d_in, const int* in_sizes, int n_in,
                              void* d_out, int out_size) {
    const float* pred_prob    = (const float*)d_in[0];
    const float* special_cost = (const float*)d_in[1];
    const int*   src          = (const int*)d_in[2];
    const int*   dst          = (const int*)d_in[3];
    float*       out          = (float*)d_out;

    const int N = in_sizes[0];   // num nodes (divisible by 4 here)
    const int E = in_sizes[2];   // num edges

    {
        int n4 = N / 4;                 // N = 1,000,000 -> exact
        int threads = 512;
        int blocks = (n4 + threads - 1) / threads;
        init_kernel<<<blocks, threads>>>(out, n4);
    }
    {
        int threads = 512;
        int work = (E + 7) / 8;
        int blocks = (work + threads - 1) / threads;
        scatter_kernel<<<blocks, threads>>>(pred_prob, src, dst, out, E);
    }
    {
        int n4 = N / 4;
        int threads = 512;
        int blocks = (n4 + threads - 1) / threads;
        apply_kernel<<<blocks, threads>>>(out, special_cost, n4);
    }
}

// round 7
// speedup vs baseline: 1.0450x; 1.0450x over previous
#include <cuda_runtime.h>
#include <cuda_bf16.h>
#include <cstdint>

// ---------------------------------------------------------------------------
// out[n] = (segment_sum(pred_prob[src], dst)[n] - 1)^2 * special_cost[n]
// N = 1,000,000 nodes, E = 16,000,000 edges.
//
// v6: no init kernel, no host API calls in kernel_launch beyond launches.
// Scatter accumulates into a zero-initialized __device__ scratch referenced
// directly by the kernels; apply computes (a-1)^2*cost into d_out AND resets
// the scratch to 0, restoring the invariant for the next (graph-replayed)
// call. Scatter uses the measured-best R2 shape: 4 edges/thread, 256
// threads, atomicAdd (emits RED).
//
// Bottleneck model (calibrated R2/R3): scatter is L1tex-wavefront bound,
// ~2.3 cyc/edge/SM (32 random gather lines + spread RED per warp).
// ---------------------------------------------------------------------------

#define MAX_NODES 1000000
__device__ float g_accum[MAX_NODES];   // static zero-init

__global__ __launch_bounds__(256) void scatter_accum_kernel(
        const float* __restrict__ pred_prob,
        const int*   __restrict__ src,
        const int*   __restrict__ dst,
        int num_edges) {
    int i = blockIdx.x * blockDim.x + threadIdx.x;
    int base = i * 4;
    if (base + 3 < num_edges) {
        int4 s4 = *reinterpret_cast<const int4*>(src + base);
        int4 d4 = *reinterpret_cast<const int4*>(dst + base);
        float m0 = __ldg(pred_prob + s4.x);
        float m1 = __ldg(pred_prob + s4.y);
        float m2 = __ldg(pred_prob + s4.z);
        float m3 = __ldg(pred_prob + s4.w);
        atomicAdd(g_accum + d4.x, m0);   // return unused -> RED
        atomicAdd(g_accum + d4.y, m1);
        atomicAdd(g_accum + d4.z, m2);
        atomicAdd(g_accum + d4.w, m3);
    } else {
        for (int e = base; e < num_edges; ++e) {
            atomicAdd(g_accum + dst[e], __ldg(pred_prob + src[e]));
        }
    }
}

// Reads accumulated sums, computes (a-1)^2 * cost into out, and resets the
// accumulator to zero so the next call starts from the same state.
__global__ __launch_bounds__(256) void apply_reset_kernel(
        const float* __restrict__ special_cost,
        float*       __restrict__ out,
        int n) {
    int i = blockIdx.x * blockDim.x + threadIdx.x;
    int base = i * 4;
    if (base + 3 < n) {
        float4 a = *reinterpret_cast<const float4*>(g_accum + base);
        float4 c = *reinterpret_cast<const float4*>(special_cost + base);
        float4 r;
        float h;
        h = a.x - 1.0f; r.x = h * h * c.x;
        h = a.y - 1.0f; r.y = h * h * c.y;
        h = a.z - 1.0f; r.z = h * h * c.z;
        h = a.w - 1.0f; r.w = h * h * c.w;
        *reinterpret_cast<float4*>(out + base) = r;
        *reinterpret_cast<float4*>(g_accum + base) =
            make_float4(0.0f, 0.0f, 0.0f, 0.0f);
    } else {
        for (int k = base; k < n; ++k) {
            float h = g_accum[k] - 1.0f;
            out[k] = h * h * special_cost[k];
            g_accum[k] = 0.0f;
        }
    }
}

// Fallback path (N > MAX_NODES): classic init/scatter/apply on d_out.
__global__ __launch_bounds__(256) void init_kernel(float* __restrict__ out, int n) {
    int i = blockIdx.x * blockDim.x + threadIdx.x;
    int base = i * 4;
    if (base + 3 < n) {
        *reinterpret_cast<float4*>(out + base) =
            make_float4(-1.0f, -1.0f, -1.0f, -1.0f);
    } else {
        for (int k = base; k < n; ++k) out[k] = -1.0f;
    }
}

__global__ __launch_bounds__(256) void scatter_out_kernel(
        const float* __restrict__ pred_prob,
        const int*   __restrict__ src,
        const int*   __restrict__ dst,
        float*       __restrict__ out,
        int num_edges) {
    int i = blockIdx.x * blockDim.x + threadIdx.x;
    int base = i * 4;
    if (base + 3 < num_edges) {
        int4 s4 = *reinterpret_cast<const int4*>(src + base);
        int4 d4 = *reinterpret_cast<const int4*>(dst + base);
        atomicAdd(out + d4.x, __ldg(pred_prob + s4.x));
        atomicAdd(out + d4.y, __ldg(pred_prob + s4.y));
        atomicAdd(out + d4.z, __ldg(pred_prob + s4.z));
        atomicAdd(out + d4.w, __ldg(pred_prob + s4.w));
    } else {
        for (int e = base; e < num_edges; ++e) {
            atomicAdd(out + dst[e], __ldg(pred_prob + src[e]));
        }
    }
}

__global__ __launch_bounds__(256) void apply_inplace_kernel(
        float* __restrict__ out,
        const float* __restrict__ special_cost,
        int n) {
    int i = blockIdx.x * blockDim.x + threadIdx.x;
    int base = i * 4;
    if (base + 3 < n) {
        float4 h = *reinterpret_cast<const float4*>(out + base);
        float4 c = *reinterpret_cast<const float4*>(special_cost + base);
        h.x = h.x * h.x * c.x;
        h.y = h.y * h.y * c.y;
        h.z = h.z * h.z * c.z;
        h.w = h.w * h.w * c.w;
        *reinterpret_cast<float4*>(out + base) = h;
    } else {
        for (int k = base; k < n; ++k) {
            float h = out[k];
            out[k] = h * h * special_cost[k];
        }
    }
}

extern "C" void kernel_launch(void* const* d_in, const int* in_sizes, int n_in,
                              void* d_out, int out_size) {
    const float* pred_prob    = (const float*)d_in[0];
    const float* special_cost = (const float*)d_in[1];
    const int*   src          = (const int*)d_in[2];
    const int*   dst          = (const int*)d_in[3];
    float*       out          = (float*)d_out;

    const int N = in_sizes[0];
    const int E = in_sizes[2];

    const int threads = 256;
    int eblocks = ((E + 3) / 4 + threads - 1) / threads;
    int nblocks = ((N + 3) / 4 + threads - 1) / threads;

    if (N <= MAX_NODES) {
        scatter_accum_kernel<<<eblocks, threads>>>(pred_prob, src, dst, E);
        apply_reset_kernel<<<nblocks, threads>>>(special_cost, out, N);
    } else {
        init_kernel<<<nblocks, threads>>>(out, N);
        scatter_out_kernel<<<eblocks, threads>>>(pred_prob, src, dst, out, E);
        apply_inplace_kernel<<<nblocks, threads>>>(out, special_cost, N);
    }
}